// round 1
// baseline (speedup 1.0000x reference)
#include <cuda_runtime.h>

// E3Hamiltonian: out[n, off + p*m + j] = sum_mm cg[j*m+mm] * in[n, off + p*m + mm]
// Blocks: ss(off0,np6,m1) sp(off6,np9,m3) sd(off33,np6,m5)
//         pp(off63,np6,m9) pd(off117,np6,m15) dd(off207,np3,m25)   ROW=282

#define ROW 282
#define TILE 32
#define THREADS 256
#define TILE_FLOATS (TILE * ROW)      // 9024
#define TILE_F4     (TILE_FLOATS / 4) // 2256  (tile byte size 36096 = 16B aligned)

// padded CG layout in smem (rows padded to multiple of 4 floats, zero-filled)
// type: m, mp, base (floats)
//  ss : 1,  4,   0
//  sp : 3,  4,   4
//  sd : 5,  8,  16
//  pp : 9, 12,  56
//  pd :15, 16, 164
//  dd :25, 28, 404   -> total 1104 floats
#define CG_TOTAL 1104

// One m x m matvec, in place on this lane's row. cg rows padded to MP, 16B aligned.
template <int M, int MP>
__device__ __forceinline__ void task(float* __restrict__ r,
                                     const float* __restrict__ cg, int col) {
    float in[M];
#pragma unroll
    for (int mm = 0; mm < M; mm++) in[mm] = r[col + mm];
#pragma unroll
    for (int j = 0; j < M; j++) {
        const float4* c4 = reinterpret_cast<const float4*>(cg + j * MP);
        float acc = 0.f;
#pragma unroll
        for (int k = 0; k < MP / 4; k++) {
            float4 c = c4[k];
            if (4 * k + 0 < M) acc += c.x * in[4 * k + 0];
            if (4 * k + 1 < M) acc += c.y * in[4 * k + 1];
            if (4 * k + 2 < M) acc += c.z * in[4 * k + 2];
            if (4 * k + 3 < M) acc += c.w * in[4 * k + 3];
        }
        r[col + j] = acc;  // in[] already in registers; in-place safe
    }
}

__device__ __forceinline__ void fill_cg(float* __restrict__ dst, const float* __restrict__ src,
                                        int m, int mp, int tid) {
    int total = m * mp;
    for (int i = tid; i < total; i += THREADS) {
        int row = i / mp, c = i - row * mp;
        dst[i] = (c < m) ? src[row * m + c] : 0.f;
    }
}

__global__ __launch_bounds__(THREADS, 4)
void e3h_kernel(const float* __restrict__ ef,
                const float* __restrict__ cg_ss, const float* __restrict__ cg_sp,
                const float* __restrict__ cg_sd, const float* __restrict__ cg_pp,
                const float* __restrict__ cg_pd, const float* __restrict__ cg_dd,
                float* __restrict__ out, int n) {
    __shared__ __align__(16) float s_tile[TILE_FLOATS];
    __shared__ __align__(16) float s_cg[CG_TOTAL];

    const int tid = threadIdx.x;

    // ---- load CG matrices to smem (padded rows, zero-filled padding) ----
    fill_cg(s_cg + 0,   cg_ss, 1, 4,  tid);
    fill_cg(s_cg + 4,   cg_sp, 3, 4,  tid);
    fill_cg(s_cg + 16,  cg_sd, 5, 8,  tid);
    fill_cg(s_cg + 56,  cg_pp, 9, 12, tid);
    fill_cg(s_cg + 164, cg_pd, 15, 16, tid);
    fill_cg(s_cg + 404, cg_dd, 25, 28, tid);

    const int tile  = blockIdx.x;
    const long base = (long)tile * TILE_FLOATS;
    const int edges = min(TILE, n - tile * TILE);

    // ---- coalesced global -> smem tile load ----
    if (edges == TILE) {
        const float4* g4 = reinterpret_cast<const float4*>(ef + base);
        float4* s4 = reinterpret_cast<float4*>(s_tile);
        for (int i = tid; i < TILE_F4; i += THREADS) s4[i] = g4[i];
    } else {
        int cnt = edges * ROW;
        for (int i = tid; i < cnt; i += THREADS) s_tile[i] = ef[base + i];
    }
    __syncthreads();

    // ---- compute: lane = edge (row), warp = task bundle, in-place in smem ----
    const int lane = tid & 31;
    const int warp = tid >> 5;
    float* r = s_tile + lane * ROW;

    switch (warp) {
        case 0: task<25, 28>(r, s_cg + 404, 207); break;
        case 1: task<25, 28>(r, s_cg + 404, 232); break;
        case 2: task<25, 28>(r, s_cg + 404, 257); break;
        case 3: task<15, 16>(r, s_cg + 164, 117);
                task<15, 16>(r, s_cg + 164, 132); break;
        case 4: task<15, 16>(r, s_cg + 164, 147);
                task<15, 16>(r, s_cg + 164, 162); break;
        case 5: task<15, 16>(r, s_cg + 164, 177);
                task<15, 16>(r, s_cg + 164, 192); break;
        case 6: {
#pragma unroll
            for (int p = 0; p < 5; p++) task<9, 12>(r, s_cg + 56, 63 + 9 * p);
            break;
        }
        default: {  // warp 7
            task<9, 12>(r, s_cg + 56, 108);
#pragma unroll
            for (int p = 0; p < 6; p++) task<5, 8>(r, s_cg + 16, 33 + 5 * p);
#pragma unroll
            for (int p = 0; p < 9; p++) task<3, 4>(r, s_cg + 4, 6 + 3 * p);
#pragma unroll
            for (int p = 0; p < 6; p++) task<1, 4>(r, s_cg + 0, p);
            break;
        }
    }
    __syncthreads();

    // ---- coalesced smem -> global store ----
    if (edges == TILE) {
        const float4* s4 = reinterpret_cast<const float4*>(s_tile);
        float4* g4 = reinterpret_cast<float4*>(out + base);
        for (int i = tid; i < TILE_F4; i += THREADS) g4[i] = s4[i];
    } else {
        int cnt = edges * ROW;
        for (int i = tid; i < cnt; i += THREADS) out[base + i] = s_tile[i];
    }
}

extern "C" void kernel_launch(void* const* d_in, const int* in_sizes, int n_in,
                              void* d_out, int out_size) {
    const float* ef    = (const float*)d_in[0];
    const float* cg_ss = (const float*)d_in[1];
    const float* cg_sp = (const float*)d_in[2];
    const float* cg_sd = (const float*)d_in[3];
    const float* cg_pp = (const float*)d_in[4];
    const float* cg_pd = (const float*)d_in[5];
    const float* cg_dd = (const float*)d_in[6];
    float* out = (float*)d_out;

    int n = in_sizes[0] / ROW;
    int grid = (n + TILE - 1) / TILE;
    e3h_kernel<<<grid, THREADS>>>(ef, cg_ss, cg_sp, cg_sd, cg_pp, cg_pd, cg_dd, out, n);
}

// round 2
// speedup vs baseline: 1.3005x; 1.3005x over previous
#include <cuda_runtime.h>
#include <cstdint>
#include <cstddef>

// E3Hamiltonian: block-diagonal per-edge transform, ROW=282 floats per edge.
// out[n, off + p*m + j] = sum_mm cg[j*m+mm] * in[n, off + p*m + mm]
// Blocks: ss(off0,np6,m1) sp(off6,np9,m3) sd(off33,np6,m5)
//         pp(off63,np6,m9) pd(off117,np6,m15) dd(off207,np3,m25)

#define ROW 282
#define TILE 32
#define THREADS 256
#define TILE_FLOATS (TILE * ROW)          // 9024
#define TILE_BYTES  (TILE_FLOATS * 4)     // 36096 (16B aligned)
#define CG_TOTAL 1104
#define SMEM_TOTAL (2 * TILE_BYTES + CG_TOTAL * 4 + 16)  // 76624 B

// ---------------- PTX helpers ----------------
__device__ __forceinline__ uint32_t smem_u32(const void* p) {
    return (uint32_t)__cvta_generic_to_shared(p);
}
__device__ __forceinline__ void mbar_init(uint32_t mbar, uint32_t count) {
    asm volatile("mbarrier.init.shared.b64 [%0], %1;" :: "r"(mbar), "r"(count) : "memory");
}
__device__ __forceinline__ void mbar_expect_tx(uint32_t mbar, uint32_t bytes) {
    asm volatile("mbarrier.arrive.expect_tx.shared::cta.b64 _, [%0], %1;"
                 :: "r"(mbar), "r"(bytes) : "memory");
}
__device__ __forceinline__ void mbar_wait(uint32_t mbar, uint32_t parity) {
    asm volatile(
        "{\n\t.reg .pred P;\n\t"
        "WL_%=:\n\t"
        "mbarrier.try_wait.parity.acquire.cta.shared::cta.b64 P, [%0], %1, 0x989680;\n\t"
        "@P bra.uni WD_%=;\n\t"
        "bra.uni WL_%=;\n\t"
        "WD_%=:\n\t}"
        :: "r"(mbar), "r"(parity) : "memory");
}
__device__ __forceinline__ void tma_load_1d(uint32_t dst_smem, const void* src_gmem,
                                            uint32_t bytes, uint32_t mbar) {
    asm volatile(
        "cp.async.bulk.shared::cta.global.mbarrier::complete_tx::bytes [%0], [%1], %2, [%3];"
        :: "r"(dst_smem), "l"(src_gmem), "r"(bytes), "r"(mbar) : "memory");
}
__device__ __forceinline__ void tma_store_1d(void* dst_gmem, uint32_t src_smem, uint32_t bytes) {
    asm volatile(
        "cp.async.bulk.global.shared::cta.bulk_group [%0], [%1], %2;"
        :: "l"(dst_gmem), "r"(src_smem), "r"(bytes) : "memory");
}
__device__ __forceinline__ void tma_commit() {
    asm volatile("cp.async.bulk.commit_group;" ::: "memory");
}
__device__ __forceinline__ void tma_wait_all() {
    asm volatile("cp.async.bulk.wait_group 0;" ::: "memory");
}
__device__ __forceinline__ void fence_async_shared() {
    asm volatile("fence.proxy.async.shared::cta;" ::: "memory");
}

// ---------------- compute ----------------
// One m x m matvec, in place on this lane's row. cg rows padded to MP (16B).
template <int M, int MP>
__device__ __forceinline__ void task(float* __restrict__ r,
                                     const float* __restrict__ cg, int col) {
    float in[M];
#pragma unroll
    for (int mm = 0; mm < M; mm++) in[mm] = r[col + mm];
#pragma unroll
    for (int j = 0; j < M; j++) {
        const float4* c4 = reinterpret_cast<const float4*>(cg + j * MP);
        float acc = 0.f;
#pragma unroll
        for (int k = 0; k < MP / 4; k++) {
            float4 c = c4[k];
            if (4 * k + 0 < M) acc += c.x * in[4 * k + 0];
            if (4 * k + 1 < M) acc += c.y * in[4 * k + 1];
            if (4 * k + 2 < M) acc += c.z * in[4 * k + 2];
            if (4 * k + 3 < M) acc += c.w * in[4 * k + 3];
        }
        r[col + j] = acc;
    }
}

// warp-partitioned task dispatch; warps own disjoint column ranges, lane = edge.
__device__ __forceinline__ void compute_row(float* __restrict__ r,
                                            const float* __restrict__ s_cg, int warp) {
    switch (warp) {
        case 0: task<25, 28>(r, s_cg + 404, 207); break;
        case 1: task<25, 28>(r, s_cg + 404, 232); break;
        case 2: task<25, 28>(r, s_cg + 404, 257); break;
        case 3: task<15, 16>(r, s_cg + 164, 117);
                task<15, 16>(r, s_cg + 164, 132); break;
        case 4: task<15, 16>(r, s_cg + 164, 147);
                task<15, 16>(r, s_cg + 164, 162); break;
        case 5: task<15, 16>(r, s_cg + 164, 177);
                task<15, 16>(r, s_cg + 164, 192); break;
        case 6: {
#pragma unroll
            for (int p = 0; p < 5; p++) task<9, 12>(r, s_cg + 56, 63 + 9 * p);
            break;
        }
        default: {  // warp 7
            task<9, 12>(r, s_cg + 56, 108);
#pragma unroll
            for (int p = 0; p < 6; p++) task<5, 8>(r, s_cg + 16, 33 + 5 * p);
#pragma unroll
            for (int p = 0; p < 9; p++) task<3, 4>(r, s_cg + 4, 6 + 3 * p);
#pragma unroll
            for (int p = 0; p < 6; p++) task<1, 4>(r, s_cg + 0, p);
            break;
        }
    }
}

__device__ __forceinline__ void fill_cg(float* __restrict__ dst, const float* __restrict__ src,
                                        int m, int mp, int tid) {
    int total = m * mp;
    for (int i = tid; i < total; i += THREADS) {
        int row = i / mp, c = i - row * mp;
        dst[i] = (c < m) ? src[row * m + c] : 0.f;
    }
}

extern __shared__ __align__(128) unsigned char dynsmem[];

__global__ __launch_bounds__(THREADS, 2)
void e3h_kernel(const float* __restrict__ ef,
                const float* __restrict__ cg_ss, const float* __restrict__ cg_sp,
                const float* __restrict__ cg_sd, const float* __restrict__ cg_pp,
                const float* __restrict__ cg_pd, const float* __restrict__ cg_dd,
                float* __restrict__ out, int n, int ntiles) {
    float* buf0 = reinterpret_cast<float*>(dynsmem);
    float* buf1 = buf0 + TILE_FLOATS;
    float* s_cg = buf1 + TILE_FLOATS;
    unsigned long long* mb = reinterpret_cast<unsigned long long*>(s_cg + CG_TOTAL);

    const int tid = threadIdx.x;
    const int lane = tid & 31;
    const int warp = tid >> 5;

    // CG -> smem (padded rows, zero fill); mbarrier init
    fill_cg(s_cg + 0,   cg_ss, 1, 4,  tid);
    fill_cg(s_cg + 4,   cg_sp, 3, 4,  tid);
    fill_cg(s_cg + 16,  cg_sd, 5, 8,  tid);
    fill_cg(s_cg + 56,  cg_pp, 9, 12, tid);
    fill_cg(s_cg + 164, cg_pd, 15, 16, tid);
    fill_cg(s_cg + 404, cg_dd, 25, 28, tid);
    const uint32_t mbad0 = smem_u32(mb);
    const uint32_t mbad1 = smem_u32(mb + 1);
    const uint32_t sb0 = smem_u32(buf0);
    const uint32_t sb1 = smem_u32(buf1);
    if (tid == 0) { mbar_init(mbad0, 1); mbar_init(mbad1, 1); }
    __syncthreads();

    const int bid = blockIdx.x;
    const int grid = gridDim.x;
    const int cnt = (bid < ntiles) ? (ntiles - bid + grid - 1) / grid : 0;

    if (cnt > 0 && tid == 0) {
        mbar_expect_tx(mbad0, TILE_BYTES);
        tma_load_1d(sb0, ef + (size_t)bid * TILE_FLOATS, TILE_BYTES, mbad0);
    }

    for (int k = 0; k < cnt; k++) {
        const size_t tile = (size_t)bid + (size_t)k * grid;
        if (tid == 0 && k + 1 < cnt) {
            // buffer (k+1)&1 was last read by store of tile k-1 -> drain stores first
            tma_wait_all();
            const uint32_t mbn = ((k + 1) & 1) ? mbad1 : mbad0;
            const uint32_t sbn = ((k + 1) & 1) ? sb1 : sb0;
            mbar_expect_tx(mbn, TILE_BYTES);
            tma_load_1d(sbn, ef + (tile + grid) * TILE_FLOATS, TILE_BYTES, mbn);
        }
        // wait current tile's data
        mbar_wait((k & 1) ? mbad1 : mbad0, (k >> 1) & 1);

        float* s = (k & 1) ? buf1 : buf0;
        compute_row(s + lane * ROW, s_cg, warp);   // warps own disjoint columns
        __syncthreads();

        if (tid == 0) {
            fence_async_shared();
            tma_store_1d(out + tile * TILE_FLOATS, (k & 1) ? sb1 : sb0, TILE_BYTES);
            tma_commit();
        }
    }

    // ---- remainder edges (n % TILE), handled by block 0 with plain ld/st ----
    const int rem = n - ntiles * TILE;
    if (rem > 0 && bid == 0) {
        if (tid == 0) tma_wait_all();
        __syncthreads();
        const size_t base = (size_t)ntiles * TILE_FLOATS;
        const int cntf = rem * ROW;
        for (int i = tid; i < cntf; i += THREADS) buf0[i] = ef[base + i];
        __syncthreads();
        if (lane < rem) compute_row(buf0 + lane * ROW, s_cg, warp);
        __syncthreads();
        for (int i = tid; i < cntf; i += THREADS) out[base + i] = buf0[i];
    }

    if (tid == 0) tma_wait_all();   // ensure bulk stores complete before exit
}

extern "C" void kernel_launch(void* const* d_in, const int* in_sizes, int n_in,
                              void* d_out, int out_size) {
    const float* ef    = (const float*)d_in[0];
    const float* cg_ss = (const float*)d_in[1];
    const float* cg_sp = (const float*)d_in[2];
    const float* cg_sd = (const float*)d_in[3];
    const float* cg_pp = (const float*)d_in[4];
    const float* cg_pd = (const float*)d_in[5];
    const float* cg_dd = (const float*)d_in[6];
    float* out = (float*)d_out;

    int n = in_sizes[0] / ROW;
    int ntiles = n / TILE;

    int sms = 148;
    cudaDeviceGetAttribute(&sms, cudaDevAttrMultiProcessorCount, 0);
    int grid = 2 * sms;
    if (ntiles > 0 && grid > ntiles) grid = ntiles;
    if (grid < 1) grid = 1;

    cudaFuncSetAttribute(e3h_kernel, cudaFuncAttributeMaxDynamicSharedMemorySize, SMEM_TOTAL);
    e3h_kernel<<<grid, THREADS, SMEM_TOTAL>>>(ef, cg_ss, cg_sp, cg_sd, cg_pp, cg_pd, cg_dd,
                                              out, n, ntiles);
}